// round 2
// baseline (speedup 1.0000x reference)
#include <cuda_runtime.h>
#include <math.h>

// Problem constants
#define NB      16
#define NS      4096
#define NDM     768
#define NH      8
#define NDA     96
#define CHUNK   128
#define NSPLITS (NS / CHUNK)        // 32
#define THREADS 128

// Split-softmax scratch (no allocations allowed -> __device__ globals)
__device__ float g_acc[NB * NH * NSPLITS * NDA];   // partial weighted sums
__device__ float g_ml [NB * NH * NSPLITS * 2];     // (m, l) per partial

// -------------------------------------------------------------------------
// Pass 1: one block = one (b,h) x one 128-row chunk of S.
// Loads K-tile to SMEM once, computes scores, local softmax, and the
// partial weighted accumulation of (K + positional encoding).
// -------------------------------------------------------------------------
__global__ __launch_bounds__(THREADS) void attn_pass1(
    const float* __restrict__ src,
    const unsigned char* __restrict__ mask,
    const float* __restrict__ query)
{
    extern __shared__ float sm[];
    float* tile = sm;                    // CHUNK * NDA floats
    float* sc   = sm + CHUNK * NDA;      // CHUNK floats (scores -> weights)
    float* red  = sc + CHUNK;            // 4 * NDA floats (reductions)

    const int bid   = blockIdx.x;
    const int split = bid & (NSPLITS - 1);
    const int bh    = bid >> 5;          // NSPLITS == 32
    const int b     = bh >> 3;           // NH == 8
    const int h     = bh & 7;
    const int s0    = split * CHUNK;
    const int tid   = threadIdx.x;
    const int lane  = tid & 31;
    const int wrp   = tid >> 5;

    // ---- Load tile: rows (s0..s0+127), cols (h*96..h*96+95), float4 ----
    const float4* g = (const float4*)src
                    + ((size_t)b * NS + s0) * (NDM / 4) + h * (NDA / 4);
    #pragma unroll
    for (int it = 0; it < (CHUNK * (NDA / 4)) / THREADS; it++) {
        int idx = tid + it * THREADS;
        int r   = idx / (NDA / 4);
        int c   = idx - r * (NDA / 4);
        float4 v = __ldg(&g[(size_t)r * (NDM / 4) + c]);
        *(float4*)(tile + r * NDA + c * 4) = v;
    }

    // query values for this lane's 3 columns
    const float q0 = query[h * NDA + lane];
    const float q1 = query[h * NDA + lane + 32];
    const float q2 = query[h * NDA + lane + 64];
    __syncthreads();

    // ---- Scores: warp 'wrp' handles rows [wrp*32, wrp*32+32) ----
    #pragma unroll 4
    for (int rr = 0; rr < 32; rr++) {
        int r = (wrp << 5) + rr;
        const float* row = tile + r * NDA;
        float p = row[lane] * q0 + row[lane + 32] * q1 + row[lane + 64] * q2;
        #pragma unroll
        for (int o = 16; o; o >>= 1) p += __shfl_xor_sync(0xffffffffu, p, o);
        if (lane == 0) sc[r] = p;
    }
    __syncthreads();

    // ---- Local softmax over the 128 rows ----
    float v = sc[tid];
    if (mask[(size_t)b * NS + s0 + tid]) v = -INFINITY;
    float m = v;
    #pragma unroll
    for (int o = 16; o; o >>= 1) m = fmaxf(m, __shfl_xor_sync(0xffffffffu, m, o));
    if (lane == 0) red[wrp] = m;
    __syncthreads();
    m = fmaxf(fmaxf(red[0], red[1]), fmaxf(red[2], red[3]));

    float wv = (v == -INFINITY) ? 0.0f : expf(v - m);
    float lsum = wv;
    #pragma unroll
    for (int o = 16; o; o >>= 1) lsum += __shfl_xor_sync(0xffffffffu, lsum, o);
    if (lane == 0) red[4 + wrp] = lsum;
    __syncthreads();
    const float l = red[4] + red[5] + red[6] + red[7];
    sc[tid] = wv;                         // scores -> weights (in place)
    __syncthreads();

    // ---- Accumulate: lane owns cols {lane, lane+32, lane+64} for its
    //      warp's 32 rows. PE via rotation recurrence (4 FMA / step). ----
    const float NEGI = -9.210340371976184f / 384.0f;  // -ln(1e4)*2/768
    const float SCAL = 0.03608439182435161f;          // 768^-0.5
    const bool  odd  = (lane & 1) != 0;               // parity of col index

    float sn[3], cs[3], ss[3], cc[3];
    const float pos0 = (float)(s0 + (wrp << 5));
    #pragma unroll
    for (int k = 0; k < 3; k++) {
        int j = h * NDA + lane + 32 * k;
        int i = j >> 1;
        float f = expf(NEGI * (float)i);
        sincosf(pos0 * f, &sn[k], &cs[k]);   // state at first row
        sincosf(f,        &ss[k], &cc[k]);   // per-row rotation step
    }

    float a0 = 0.0f, a1 = 0.0f, a2 = 0.0f;
    #pragma unroll 4
    for (int rr = 0; rr < 32; rr++) {
        int r = (wrp << 5) + rr;
        float wgt = sc[r];
        const float* row = tile + r * NDA;
        float pe0 = odd ? cs[0] : sn[0];
        float pe1 = odd ? cs[1] : sn[1];
        float pe2 = odd ? cs[2] : sn[2];
        a0 = fmaf(wgt, fmaf(SCAL, pe0, row[lane])      , a0);
        a1 = fmaf(wgt, fmaf(SCAL, pe1, row[lane + 32]) , a1);
        a2 = fmaf(wgt, fmaf(SCAL, pe2, row[lane + 64]) , a2);
        #pragma unroll
        for (int k = 0; k < 3; k++) {
            float nsn = fmaf(sn[k], cc[k],  cs[k] * ss[k]);
            float ncs = fmaf(cs[k], cc[k], -sn[k] * ss[k]);
            sn[k] = nsn; cs[k] = ncs;
        }
    }

    // cross-warp reduce of the 96 accumulators
    red[wrp * NDA + lane]      = a0;
    red[wrp * NDA + lane + 32] = a1;
    red[wrp * NDA + lane + 64] = a2;
    __syncthreads();

    if (tid < NDA) {
        float a = red[tid] + red[NDA + tid] + red[2 * NDA + tid] + red[3 * NDA + tid];
        g_acc[(size_t)bid * NDA + tid] = a;
    }
    if (tid == 0) {
        g_ml[bid * 2]     = m;
        g_ml[bid * 2 + 1] = l;
    }
}

// -------------------------------------------------------------------------
// Pass 2: merge the 32 split partials per (b,h).
// -------------------------------------------------------------------------
__global__ __launch_bounds__(NDA) void attn_pass2(float* __restrict__ out)
{
    const int bh   = blockIdx.x;
    const int d    = threadIdx.x;          // 96 threads
    const int base = bh * NSPLITS;

    float M = -INFINITY;
    #pragma unroll
    for (int i = 0; i < NSPLITS; i++) M = fmaxf(M, g_ml[(base + i) * 2]);

    float L = 0.0f, A = 0.0f;
    #pragma unroll 4
    for (int i = 0; i < NSPLITS; i++) {
        float e = expf(g_ml[(base + i) * 2] - M);
        L = fmaf(e, g_ml[(base + i) * 2 + 1], L);
        A = fmaf(e, g_acc[(size_t)(base + i) * NDA + d], A);
    }
    out[bh * NDA + d] = A / L;   // bh*96+d == b*768 + h*96 + d
}

// -------------------------------------------------------------------------
extern "C" void kernel_launch(void* const* d_in, const int* in_sizes, int n_in,
                              void* d_out, int out_size)
{
    const float*         src   = (const float*)d_in[0];
    const unsigned char* mask  = (const unsigned char*)d_in[1];
    const float*         query = (const float*)d_in[2];
    float*               out   = (float*)d_out;

    const int smem_bytes = (CHUNK * NDA + CHUNK + 4 * NDA) * (int)sizeof(float); // 51200
    cudaFuncSetAttribute(attn_pass1,
                         cudaFuncAttributeMaxDynamicSharedMemorySize, smem_bytes);

    attn_pass1<<<NB * NH * NSPLITS, THREADS, smem_bytes>>>(src, mask, query);
    attn_pass2<<<NB * NH, NDA>>>(out);
}

// round 3
// speedup vs baseline: 1.0254x; 1.0254x over previous
#include <cuda_runtime.h>
#include <math.h>

// Problem constants
#define NB      16
#define NS      4096
#define NDM     768
#define NH      8
#define NDA     96
#define CHUNK   128
#define NSPLITS (NS / CHUNK)        // 32
#define THREADS 256
#define TS      100                 // padded tile row stride (floats)

// Split-softmax scratch (no allocations allowed -> __device__ globals)
__device__ float g_acc[NB * NH * NSPLITS * NDA];   // partial weighted sums
__device__ float g_ml [NB * NH * NSPLITS * 2];     // (m, l) per partial

// -------------------------------------------------------------------------
// Pass 1: one block = one (b,h) x one 128-row chunk of S.
// 256 threads / 8 warps. Tile in SMEM (padded stride), transposed score
// computation (no warp reductions), split-softmax, weighted accumulation
// of (K + sinusoidal PE) with a rotation recurrence for the PE.
// -------------------------------------------------------------------------
__global__ __launch_bounds__(THREADS) void attn_pass1(
    const float* __restrict__ src,
    const unsigned char* __restrict__ mask,
    const float* __restrict__ query)
{
    extern __shared__ float sm[];
    float* tile = sm;                        // CHUNK * TS
    float* sc   = sm + CHUNK * TS;           // CHUNK  (scores -> weights)
    float* red  = sc + CHUNK;                // 8 * NDA
    float* qsm  = red + 8 * NDA;             // NDA
    float* mr   = qsm + NDA;                 // 8
    float* lr   = mr + 8;                    // 8

    const int bid   = blockIdx.x;
    const int split = bid & (NSPLITS - 1);
    const int bh    = bid >> 5;
    const int b     = bh >> 3;
    const int h     = bh & 7;
    const int s0    = split * CHUNK;
    const int tid   = threadIdx.x;
    const int lane  = tid & 31;
    const int wrp   = tid >> 5;              // 0..7

    // query -> smem
    if (tid < NDA) qsm[tid] = query[h * NDA + tid];

    // ---- Load tile: rows (s0..s0+127), cols (h*96..h*96+95), float4 ----
    const float4* g = (const float4*)src
                    + ((size_t)b * NS + s0) * (NDM / 4) + h * (NDA / 4);
    #pragma unroll
    for (int it = 0; it < (CHUNK * (NDA / 4)) / THREADS; it++) {   // 12
        int idx = tid + it * THREADS;
        int r   = idx / (NDA / 4);
        int c   = idx - r * (NDA / 4);
        float4 v = __ldg(&g[(size_t)r * (NDM / 4) + c]);
        *(float4*)(tile + r * TS + c * 4) = v;
    }
    __syncthreads();

    // ---- Scores (transposed): thread owns (row = tid>>1, half = tid&1) ----
    {
        int r  = tid >> 1;
        int hf = tid & 1;
        const float* row = tile + r * TS + hf * 48;
        const float* qq  = qsm + hf * 48;
        float p = 0.0f;
        #pragma unroll
        for (int c = 0; c < 48; c++) p = fmaf(row[c], qq[c], p);
        p += __shfl_xor_sync(0xffffffffu, p, 1);   // pair halves (adjacent lanes)
        if (hf == 0) sc[r] = p;
    }
    __syncthreads();

    // ---- Block softmax over 128 rows ----
    float v = -INFINITY;
    if (tid < CHUNK) {
        v = sc[tid];
        if (mask[(size_t)b * NS + s0 + tid]) v = -INFINITY;
    }
    float mm = v;
    #pragma unroll
    for (int o = 16; o; o >>= 1) mm = fmaxf(mm, __shfl_xor_sync(0xffffffffu, mm, o));
    if (lane == 0) mr[wrp] = mm;               // warps 4..7 contribute -inf (neutral)
    __syncthreads();
    float M = mr[0];
    #pragma unroll
    for (int k = 1; k < 8; k++) M = fmaxf(M, mr[k]);

    float wv = (v == -INFINITY) ? 0.0f : expf(v - M);
    float ls = wv;
    #pragma unroll
    for (int o = 16; o; o >>= 1) ls += __shfl_xor_sync(0xffffffffu, ls, o);
    if (lane == 0) lr[wrp] = ls;
    __syncthreads();
    if (tid < CHUNK) sc[tid] = wv;
    if (tid == 0) {
        float L = lr[0] + lr[1] + lr[2] + lr[3] + lr[4] + lr[5] + lr[6] + lr[7];
        g_ml[bid * 2]     = M;
        g_ml[bid * 2 + 1] = L;
    }
    __syncthreads();

    // ---- Accumulate: warp w owns rows [w*16, w*16+16); lane owns cols
    //      {lane, lane+32, lane+64}. PE via rotation recurrence. ----
    const float NEGI = -9.210340371976184f / 384.0f;  // -ln(1e4)*2/768
    const float SCAL = 0.03608439182435161f;          // 768^-0.5
    const bool  odd  = (lane & 1) != 0;

    float sn[3], cs[3], ss[3], cc[3];
    const float pos0 = (float)(s0 + (wrp << 4));
    #pragma unroll
    for (int k = 0; k < 3; k++) {
        int j = h * NDA + lane + 32 * k;
        int i = j >> 1;
        float f = expf(NEGI * (float)i);
        sincosf(pos0 * f, &sn[k], &cs[k]);   // state at first row
        sincosf(f,        &ss[k], &cc[k]);   // per-row rotation step
    }

    float a0 = 0.0f, a1 = 0.0f, a2 = 0.0f;
    #pragma unroll
    for (int rr = 0; rr < 16; rr++) {
        int r = (wrp << 4) + rr;
        float wgt = sc[r];
        const float* row = tile + r * TS;
        float pe0 = odd ? cs[0] : sn[0];
        float pe1 = odd ? cs[1] : sn[1];
        float pe2 = odd ? cs[2] : sn[2];
        a0 = fmaf(wgt, fmaf(SCAL, pe0, row[lane])      , a0);
        a1 = fmaf(wgt, fmaf(SCAL, pe1, row[lane + 32]) , a1);
        a2 = fmaf(wgt, fmaf(SCAL, pe2, row[lane + 64]) , a2);
        #pragma unroll
        for (int k = 0; k < 3; k++) {
            float nsn = fmaf(sn[k], cc[k],  cs[k] * ss[k]);
            float ncs = fmaf(cs[k], cc[k], -sn[k] * ss[k]);
            sn[k] = nsn; cs[k] = ncs;
        }
    }

    // cross-warp reduce of the 96 accumulators (8 partials)
    red[wrp * NDA + lane]      = a0;
    red[wrp * NDA + lane + 32] = a1;
    red[wrp * NDA + lane + 64] = a2;
    __syncthreads();

    if (tid < NDA) {
        float a = 0.0f;
        #pragma unroll
        for (int k = 0; k < 8; k++) a += red[k * NDA + tid];
        g_acc[(size_t)bid * NDA + tid] = a;
    }
}

// -------------------------------------------------------------------------
// Pass 2: merge the 32 split partials per (b,h). 8 warps x 4 splits each.
// -------------------------------------------------------------------------
__global__ __launch_bounds__(256) void attn_pass2(float* __restrict__ out)
{
    __shared__ float pA[8 * NDA];
    __shared__ float pL[8];
    __shared__ float sM;

    const int bh   = blockIdx.x;
    const int base = bh * NSPLITS;
    const int tid  = threadIdx.x;
    const int lane = tid & 31;
    const int w    = tid >> 5;

    // global max over the 32 split maxima (warp 0)
    if (w == 0) {
        float mv = g_ml[(base + lane) * 2];
        #pragma unroll
        for (int o = 16; o; o >>= 1) mv = fmaxf(mv, __shfl_xor_sync(0xffffffffu, mv, o));
        if (lane == 0) sM = mv;
    }
    __syncthreads();
    const float M = sM;

    float A0 = 0.0f, A1 = 0.0f, A2 = 0.0f, L = 0.0f;
    #pragma unroll
    for (int i = 0; i < 4; i++) {
        int s = base + w * 4 + i;
        float m = g_ml[s * 2];
        float l = g_ml[s * 2 + 1];
        float e = expf(m - M);
        L = fmaf(e, l, L);
        const float* a = g_acc + (size_t)s * NDA;
        A0 = fmaf(e, a[lane],      A0);
        A1 = fmaf(e, a[lane + 32], A1);
        A2 = fmaf(e, a[lane + 64], A2);
    }
    pA[w * NDA + lane]      = A0;
    pA[w * NDA + lane + 32] = A1;
    pA[w * NDA + lane + 64] = A2;
    if (lane == 0) pL[w] = L;
    __syncthreads();

    if (tid < NDA) {
        float A = 0.0f;
        #pragma unroll
        for (int k = 0; k < 8; k++) A += pA[k * NDA + tid];
        float Lt = pL[0] + pL[1] + pL[2] + pL[3] + pL[4] + pL[5] + pL[6] + pL[7];
        out[bh * NDA + tid] = A / Lt;
    }
}

// -------------------------------------------------------------------------
extern "C" void kernel_launch(void* const* d_in, const int* in_sizes, int n_in,
                              void* d_out, int out_size)
{
    const float*         src   = (const float*)d_in[0];
    const unsigned char* mask  = (const unsigned char*)d_in[1];
    const float*         query = (const float*)d_in[2];
    float*               out   = (float*)d_out;

    const int smem_bytes = (CHUNK * TS + CHUNK + 8 * NDA + NDA + 16) * (int)sizeof(float);
    cudaFuncSetAttribute(attn_pass1,
                         cudaFuncAttributeMaxDynamicSharedMemorySize, smem_bytes);

    attn_pass1<<<NB * NH * NSPLITS, THREADS, smem_bytes>>>(src, mask, query);
    attn_pass2<<<NB * NH, 256>>>(out);
}

// round 4
// speedup vs baseline: 1.1829x; 1.1536x over previous
#include <cuda_runtime.h>
#include <math.h>

// Problem constants
#define NB      16
#define NS      4096
#define NDM     768
#define NH      8
#define NDA     96
#define CHUNK   128
#define NSPLITS (NS / CHUNK)        // 32
#define THREADS 256
#define TS      100                 // padded tile row stride (floats)

// Scratch (no allocations allowed -> __device__ globals)
__device__ float g_pe [NS * NDM];                  // precomputed scaled PE (12.6 MB)
__device__ float g_acc[NB * NH * NSPLITS * NDA];   // partial weighted sums
__device__ float g_ml [NB * NH * NSPLITS * 2];     // (m, l) per partial

// no-op kernel: pads the launch sequence so ncu (-s 5) profiles pass1
__global__ void knop() {}

// -------------------------------------------------------------------------
// PE init: pe[s, 2i] = scale*sin(s*f_i), pe[s, 2i+1] = scale*cos(s*f_i),
// f_i = exp(-ln(1e4)*2i/768), scale = 768^-0.5. One thread per (s, i) pair.
// -------------------------------------------------------------------------
__global__ __launch_bounds__(256) void pe_init()
{
    int idx = blockIdx.x * blockDim.x + threadIdx.x;    // [0, NS*NDM/2)
    if (idx >= NS * (NDM / 2)) return;
    int s = idx / (NDM / 2);
    int i = idx - s * (NDM / 2);
    float f = expf(-9.210340371976184f * (float)(2 * i) / (float)NDM);
    float sn, cs;
    sincosf((float)s * f, &sn, &cs);
    ((float2*)g_pe)[idx] = make_float2(0.03608439182435161f * sn,
                                       0.03608439182435161f * cs);
}

// -------------------------------------------------------------------------
// Pass 1: one block = one (b,h) x one 128-row chunk of S.
// load tile -> scores (float4, 4-way ILP) -> softmax + (tile += PE) ->
// weighted accumulate (3 FMA/row/thread) -> cross-warp reduce.
// -------------------------------------------------------------------------
__global__ __launch_bounds__(THREADS) void attn_pass1(
    const float* __restrict__ src,
    const unsigned char* __restrict__ mask,
    const float* __restrict__ query)
{
    extern __shared__ float sm[];
    float* tile = sm;                        // CHUNK * TS
    float* sc   = sm + CHUNK * TS;           // CHUNK  (scores -> weights)
    float* red  = sc + CHUNK;                // 8 * NDA
    float* qsm  = red + 8 * NDA;             // NDA
    float* mr   = qsm + NDA;                 // 8
    float* lr   = mr + 8;                    // 8

    const int bid   = blockIdx.x;
    const int split = bid & (NSPLITS - 1);
    const int bh    = bid >> 5;
    const int b     = bh >> 3;
    const int h     = bh & 7;
    const int s0    = split * CHUNK;
    const int tid   = threadIdx.x;
    const int lane  = tid & 31;
    const int wrp   = tid >> 5;              // 0..7

    if (tid < NDA) qsm[tid] = query[h * NDA + tid];

    // ---- Load tile: rows (s0..s0+127), cols (h*96..h*96+95), float4 ----
    const float4* g = (const float4*)src
                    + ((size_t)b * NS + s0) * (NDM / 4) + h * (NDA / 4);
    #pragma unroll
    for (int it = 0; it < (CHUNK * (NDA / 4)) / THREADS; it++) {   // 12
        int idx = tid + it * THREADS;
        int r   = idx / (NDA / 4);
        int c   = idx - r * (NDA / 4);
        float4 v = __ldg(&g[(size_t)r * (NDM / 4) + c]);
        *(float4*)(tile + r * TS + c * 4) = v;
    }
    __syncthreads();

    // ---- Scores: thread owns (row = tid>>1, half = tid&1), float4 ILP ----
    {
        int r  = tid >> 1;
        int hf = tid & 1;
        const float4* row4 = (const float4*)(tile + r * TS + hf * 48);
        const float4* q4   = (const float4*)(qsm + hf * 48);
        float p0 = 0.f, p1 = 0.f, p2 = 0.f, p3 = 0.f;
        #pragma unroll
        for (int c = 0; c < 12; c++) {
            float4 t = row4[c];
            float4 q = q4[c];
            p0 = fmaf(t.x, q.x, p0);
            p1 = fmaf(t.y, q.y, p1);
            p2 = fmaf(t.z, q.z, p2);
            p3 = fmaf(t.w, q.w, p3);
        }
        float p = (p0 + p1) + (p2 + p3);
        p += __shfl_xor_sync(0xffffffffu, p, 1);   // pair halves
        if (hf == 0) sc[r] = p;
    }
    __syncthreads();

    // ---- tile += PE (data-independent of softmax; same phase) ----
    const float4* gpe = (const float4*)g_pe
                      + (size_t)s0 * (NDM / 4) + h * (NDA / 4);
    #pragma unroll 4
    for (int it = 0; it < (CHUNK * (NDA / 4)) / THREADS; it++) {   // 12
        int idx = tid + it * THREADS;
        int r   = idx / (NDA / 4);
        int c   = idx - r * (NDA / 4);
        float4 p = __ldg(&gpe[(size_t)r * (NDM / 4) + c]);
        float4* t = (float4*)(tile + r * TS + c * 4);
        float4 v = *t;
        v.x += p.x; v.y += p.y; v.z += p.z; v.w += p.w;
        *t = v;
    }

    // ---- Block softmax over 128 rows (interleaved with PE pass) ----
    float v = -INFINITY;
    if (tid < CHUNK) {
        v = sc[tid];
        if (mask[(size_t)b * NS + s0 + tid]) v = -INFINITY;
    }
    float mm = v;
    #pragma unroll
    for (int o = 16; o; o >>= 1) mm = fmaxf(mm, __shfl_xor_sync(0xffffffffu, mm, o));
    if (lane == 0) mr[wrp] = mm;               // warps 4..7 contribute -inf
    __syncthreads();
    float M = mr[0];
    #pragma unroll
    for (int k = 1; k < 8; k++) M = fmaxf(M, mr[k]);

    float wv = (v == -INFINITY) ? 0.0f : __expf(v - M);
    float ls = wv;
    #pragma unroll
    for (int o = 16; o; o >>= 1) ls += __shfl_xor_sync(0xffffffffu, ls, o);
    if (lane == 0) lr[wrp] = ls;
    if (tid < CHUNK) sc[tid] = wv;             // read after next barrier
    __syncthreads();

    if (tid == 0) {
        float L = lr[0] + lr[1] + lr[2] + lr[3] + lr[4] + lr[5] + lr[6] + lr[7];
        g_ml[bid * 2]     = M;
        g_ml[bid * 2 + 1] = L;
    }

    // ---- Accumulate: warp w owns rows [w*16, w*16+16); lane owns cols
    //      {lane, lane+32, lane+64}. Tile already contains K + PE. ----
    float a0 = 0.0f, a1 = 0.0f, a2 = 0.0f;
    #pragma unroll
    for (int rr = 0; rr < 16; rr++) {
        int r = (wrp << 4) + rr;
        float wgt = sc[r];
        const float* row = tile + r * TS;
        a0 = fmaf(wgt, row[lane],      a0);
        a1 = fmaf(wgt, row[lane + 32], a1);
        a2 = fmaf(wgt, row[lane + 64], a2);
    }

    red[wrp * NDA + lane]      = a0;
    red[wrp * NDA + lane + 32] = a1;
    red[wrp * NDA + lane + 64] = a2;
    __syncthreads();

    if (tid < NDA) {
        float a = 0.0f;
        #pragma unroll
        for (int k = 0; k < 8; k++) a += red[k * NDA + tid];
        g_acc[(size_t)bid * NDA + tid] = a;
    }
}

// -------------------------------------------------------------------------
// Pass 2: merge the 32 split partials per (b,h). 8 warps x 4 splits each.
// All loads issued up-front (MLP ~20) before the max-reduction.
// -------------------------------------------------------------------------
__global__ __launch_bounds__(256) void attn_pass2(float* __restrict__ out)
{
    __shared__ float pA[8 * NDA];
    __shared__ float pL[8];
    __shared__ float wm[8];

    const int bh   = blockIdx.x;
    const int base = bh * NSPLITS;
    const int tid  = threadIdx.x;
    const int lane = tid & 31;
    const int w    = tid >> 5;

    // preload all operands (independent loads, high MLP)
    float m[4], l[4], x0[4], x1[4], x2[4];
    #pragma unroll
    for (int i = 0; i < 4; i++) {
        int s = base + w * 4 + i;
        m[i] = g_ml[s * 2];
        l[i] = g_ml[s * 2 + 1];
        const float* a = g_acc + (size_t)s * NDA;
        x0[i] = a[lane];
        x1[i] = a[lane + 32];
        x2[i] = a[lane + 64];
    }

    // global max (m[] uniform across the warp)
    float mw = fmaxf(fmaxf(m[0], m[1]), fmaxf(m[2], m[3]));
    if (lane == 0) wm[w] = mw;
    __syncthreads();
    float M = wm[0];
    #pragma unroll
    for (int k = 1; k < 8; k++) M = fmaxf(M, wm[k]);

    float A0 = 0.f, A1 = 0.f, A2 = 0.f, L = 0.f;
    #pragma unroll
    for (int i = 0; i < 4; i++) {
        float e = __expf(m[i] - M);
        L  = fmaf(e, l[i],  L);
        A0 = fmaf(e, x0[i], A0);
        A1 = fmaf(e, x1[i], A1);
        A2 = fmaf(e, x2[i], A2);
    }
    pA[w * NDA + lane]      = A0;
    pA[w * NDA + lane + 32] = A1;
    pA[w * NDA + lane + 64] = A2;
    if (lane == 0) pL[w] = L;
    __syncthreads();

    if (tid < NDA) {
        float A = 0.0f;
        #pragma unroll
        for (int k = 0; k < 8; k++) A += pA[k * NDA + tid];
        float Lt = pL[0] + pL[1] + pL[2] + pL[3] + pL[4] + pL[5] + pL[6] + pL[7];
        out[bh * NDA + tid] = A / Lt;
    }
}

// -------------------------------------------------------------------------
extern "C" void kernel_launch(void* const* d_in, const int* in_sizes, int n_in,
                              void* d_out, int out_size)
{
    const float*         src   = (const float*)d_in[0];
    const unsigned char* mask  = (const unsigned char*)d_in[1];
    const float*         query = (const float*)d_in[2];
    float*               out   = (float*)d_out;

    const int smem_bytes = (CHUNK * TS + CHUNK + 8 * NDA + NDA + 16) * (int)sizeof(float);
    cudaFuncSetAttribute(attn_pass1,
                         cudaFuncAttributeMaxDynamicSharedMemorySize, smem_bytes);

    pe_init<<<(NS * (NDM / 2) + 255) / 256, 256>>>();
    attn_pass1<<<NB * NH * NSPLITS, THREADS, smem_bytes>>>(src, mask, query);
    attn_pass2<<<NB * NH, 256>>>(out);
    knop<<<1, 1>>>();   // pads launch sequence so ncu -s 5 profiles pass1
}

// round 6
// speedup vs baseline: 1.2698x; 1.0735x over previous
#include <cuda_runtime.h>
#include <cuda_fp16.h>
#include <math.h>

// Problem constants
#define NB      16
#define NS      4096
#define NDM     768
#define NH      8
#define NDA     96
#define CHUNK   128
#define NSPLITS (NS / CHUNK)        // 32
#define THREADS 256
#define TS      100                 // padded tile row stride (floats)

// Scratch (no allocations allowed -> __device__ globals)
__device__ __half g_peh[NS * NDM];                 // scaled PE, fp16 (6.3 MB)
__device__ float  g_acc[NB * NH * NSPLITS * NDA];  // partial weighted sums
__device__ float  g_ml [NB * NH * NSPLITS * 2];    // (m, l) per partial

// no-op: pads launch sequence so the profiled launch (index 3) is pass1
__global__ void knop() {}

// -------------------------------------------------------------------------
// PE init: pe[s, 2i] = scale*sin(s*f_i), pe[s, 2i+1] = scale*cos(s*f_i),
// f_i = exp(-ln(1e4)*2i/768), scale = 768^-0.5. fp16 storage.
// -------------------------------------------------------------------------
__global__ __launch_bounds__(256) void pe_init()
{
    int idx = blockIdx.x * blockDim.x + threadIdx.x;    // [0, NS*NDM/2)
    if (idx >= NS * (NDM / 2)) return;
    int s = idx / (NDM / 2);
    int i = idx - s * (NDM / 2);
    float f = expf(-9.210340371976184f * (float)(2 * i) / (float)NDM);
    float sn, cs;
    sincosf((float)s * f, &sn, &cs);
    ((__half2*)g_peh)[idx] = __floats2half2_rn(0.03608439182435161f * sn,
                                               0.03608439182435161f * cs);
}

// -------------------------------------------------------------------------
// Pass 1: one block = one (b,h) x one 128-row chunk of S.
// load tile -> scores (float4 ILP) -> softmax -> weighted accumulate of
// (K + PE) with PE read as fp16 straight from L2 -> cross-warp reduce.
// -------------------------------------------------------------------------
__global__ __launch_bounds__(THREADS) void attn_pass1(
    const float* __restrict__ src,
    const unsigned char* __restrict__ mask,
    const float* __restrict__ query)
{
    extern __shared__ float sm[];
    float* tile = sm;                        // CHUNK * TS
    float* sc   = sm + CHUNK * TS;           // CHUNK  (scores -> weights)
    float* red  = sc + CHUNK;                // 8 * NDA
    float* qsm  = red + 8 * NDA;             // NDA
    float* mr   = qsm + NDA;                 // 8
    float* lr   = mr + 8;                    // 8

    const int bid   = blockIdx.x;
    const int split = bid & (NSPLITS - 1);
    const int bh    = bid >> 5;
    const int b     = bh >> 3;
    const int h     = bh & 7;
    const int s0    = split * CHUNK;
    const int tid   = threadIdx.x;
    const int lane  = tid & 31;
    const int wrp   = tid >> 5;              // 0..7

    if (tid < NDA) qsm[tid] = query[h * NDA + tid];

    // ---- Load tile: rows (s0..s0+127), cols (h*96..h*96+95), float4 ----
    const float4* g = (const float4*)src
                    + ((size_t)b * NS + s0) * (NDM / 4) + h * (NDA / 4);
    #pragma unroll
    for (int it = 0; it < (CHUNK * (NDA / 4)) / THREADS; it++) {   // 12
        int idx = tid + it * THREADS;
        int r   = idx / (NDA / 4);
        int c   = idx - r * (NDA / 4);
        float4 v = __ldg(&g[(size_t)r * (NDM / 4) + c]);
        *(float4*)(tile + r * TS + c * 4) = v;
    }
    __syncthreads();

    // ---- Scores: thread owns (row = tid>>1, half = tid&1), float4 ILP ----
    {
        int r  = tid >> 1;
        int hf = tid & 1;
        const float4* row4 = (const float4*)(tile + r * TS + hf * 48);
        const float4* q4   = (const float4*)(qsm + hf * 48);
        float p0 = 0.f, p1 = 0.f, p2 = 0.f, p3 = 0.f;
        #pragma unroll
        for (int c = 0; c < 12; c++) {
            float4 t = row4[c];
            float4 q = q4[c];
            p0 = fmaf(t.x, q.x, p0);
            p1 = fmaf(t.y, q.y, p1);
            p2 = fmaf(t.z, q.z, p2);
            p3 = fmaf(t.w, q.w, p3);
        }
        float p = (p0 + p1) + (p2 + p3);
        p += __shfl_xor_sync(0xffffffffu, p, 1);   // pair halves
        if (hf == 0) sc[r] = p;
    }
    __syncthreads();

    // ---- Block softmax over 128 rows ----
    float v = -INFINITY;
    if (tid < CHUNK) {
        v = sc[tid];
        if (mask[(size_t)b * NS + s0 + tid]) v = -INFINITY;
    }
    float mm = v;
    #pragma unroll
    for (int o = 16; o; o >>= 1) mm = fmaxf(mm, __shfl_xor_sync(0xffffffffu, mm, o));
    if (lane == 0) mr[wrp] = mm;               // warps 4..7 contribute -inf
    __syncthreads();
    float M = mr[0];
    #pragma unroll
    for (int k = 1; k < 8; k++) M = fmaxf(M, mr[k]);

    float wv = (v == -INFINITY) ? 0.0f : __expf(v - M);
    float ls = wv;
    #pragma unroll
    for (int o = 16; o; o >>= 1) ls += __shfl_xor_sync(0xffffffffu, ls, o);
    if (lane == 0) lr[wrp] = ls;
    if (tid < CHUNK) sc[tid] = wv;             // read after next barrier
    __syncthreads();

    if (tid == 0) {
        float L = lr[0] + lr[1] + lr[2] + lr[3] + lr[4] + lr[5] + lr[6] + lr[7];
        g_ml[bid * 2]     = M;
        g_ml[bid * 2 + 1] = L;
    }

    // ---- Accumulate: warp w owns rows [w*16, w*16+16); lane owns cols
    //      {lane, lane+32, lane+64}. PE fused in from fp16 table (L2). ----
    const __half* peb = g_peh + (size_t)s0 * NDM + h * NDA;
    float a0 = 0.0f, a1 = 0.0f, a2 = 0.0f;
    #pragma unroll
    for (int rr = 0; rr < 16; rr++) {
        int r = (wrp << 4) + rr;
        float wgt = sc[r];
        const float*  row = tile + r * TS;
        const __half* per = peb + (size_t)r * NDM;
        float p0 = __half2float(__ldg(per + lane));
        float p1 = __half2float(__ldg(per + lane + 32));
        float p2 = __half2float(__ldg(per + lane + 64));
        a0 = fmaf(wgt, row[lane]      + p0, a0);
        a1 = fmaf(wgt, row[lane + 32] + p1, a1);
        a2 = fmaf(wgt, row[lane + 64] + p2, a2);
    }

    red[wrp * NDA + lane]      = a0;
    red[wrp * NDA + lane + 32] = a1;
    red[wrp * NDA + lane + 64] = a2;
    __syncthreads();

    if (tid < NDA) {
        float a = 0.0f;
        #pragma unroll
        for (int k = 0; k < 8; k++) a += red[k * NDA + tid];
        g_acc[(size_t)bid * NDA + tid] = a;
    }
}

// -------------------------------------------------------------------------
// Pass 2: merge the 32 split partials per (b,h). 8 warps x 4 splits each.
// -------------------------------------------------------------------------
__global__ __launch_bounds__(256) void attn_pass2(float* __restrict__ out)
{
    __shared__ float pA[8 * NDA];
    __shared__ float pL[8];
    __shared__ float wm[8];

    const int bh   = blockIdx.x;
    const int base = bh * NSPLITS;
    const int tid  = threadIdx.x;
    const int lane = tid & 31;
    const int w    = tid >> 5;

    float m[4], l[4], x0[4], x1[4], x2[4];
    #pragma unroll
    for (int i = 0; i < 4; i++) {
        int s = base + w * 4 + i;
        m[i] = g_ml[s * 2];
        l[i] = g_ml[s * 2 + 1];
        const float* a = g_acc + (size_t)s * NDA;
        x0[i] = a[lane];
        x1[i] = a[lane + 32];
        x2[i] = a[lane + 64];
    }

    float mw = fmaxf(fmaxf(m[0], m[1]), fmaxf(m[2], m[3]));
    if (lane == 0) wm[w] = mw;
    __syncthreads();
    float M = wm[0];
    #pragma unroll
    for (int k = 1; k < 8; k++) M = fmaxf(M, wm[k]);

    float A0 = 0.f, A1 = 0.f, A2 = 0.f, L = 0.f;
    #pragma unroll
    for (int i = 0; i < 4; i++) {
        float e = __expf(m[i] - M);
        L  = fmaf(e, l[i],  L);
        A0 = fmaf(e, x0[i], A0);
        A1 = fmaf(e, x1[i], A1);
        A2 = fmaf(e, x2[i], A2);
    }
    pA[w * NDA + lane]      = A0;
    pA[w * NDA + lane + 32] = A1;
    pA[w * NDA + lane + 64] = A2;
    if (lane == 0) pL[w] = L;
    __syncthreads();

    if (tid < NDA) {
        float A = 0.0f;
        #pragma unroll
        for (int k = 0; k < 8; k++) A += pA[k * NDA + tid];
        float Lt = pL[0] + pL[1] + pL[2] + pL[3] + pL[4] + pL[5] + pL[6] + pL[7];
        out[bh * NDA + tid] = A / Lt;
    }
}

// -------------------------------------------------------------------------
extern "C" void kernel_launch(void* const* d_in, const int* in_sizes, int n_in,
                              void* d_out, int out_size)
{
    const float*         src   = (const float*)d_in[0];
    const unsigned char* mask  = (const unsigned char*)d_in[1];
    const float*         query = (const float*)d_in[2];
    float*               out   = (float*)d_out;

    const int smem_bytes = (CHUNK * TS + CHUNK + 8 * NDA + NDA + 16) * (int)sizeof(float);
    cudaFuncSetAttribute(attn_pass1,
                         cudaFuncAttributeMaxDynamicSharedMemorySize, smem_bytes);

    pe_init<<<(NS * (NDM / 2) + 255) / 256, 256>>>();
    knop<<<1, 1>>>();     // index padding: profiled launch (idx 3) = pass1
    knop<<<1, 1>>>();
    attn_pass1<<<NB * NH * NSPLITS, THREADS, smem_bytes>>>(src, mask, query);
    attn_pass2<<<NB * NH, 256>>>(out);
}

// round 8
// speedup vs baseline: 1.3200x; 1.0395x over previous
#include <cuda_runtime.h>
#include <cuda_fp16.h>
#include <math.h>

// Problem constants
#define NB      16
#define NS      4096
#define NDM     768
#define NH      8
#define NDA     96
#define CHUNK   64
#define NSPLITS (NS / CHUNK)        // 64
#define THREADS 256
#define TS      100                 // padded tile row stride (floats)

// Scratch (no allocations allowed -> __device__ globals)
__device__ __half g_peh[NS * NDM];                 // scaled PE, fp16 (6.3 MB)
__device__ float  g_acc[NB * NH * NSPLITS * NDA];  // partial weighted sums
__device__ float  g_ml [NB * NH * NSPLITS * 2];    // (m, l) per partial

// no-op: pads launch sequence so the profiled launch (index 3) is pass1
__global__ void knop() {}

// -------------------------------------------------------------------------
// PE init: pe[s, 2i] = scale*sin(s*f_i), pe[s, 2i+1] = scale*cos(s*f_i).
// Each thread does rows (2s, 2s+1) for one frequency: 1 sincosf + rotation.
// -------------------------------------------------------------------------
__global__ __launch_bounds__(256) void pe_init()
{
    int idx = blockIdx.x * blockDim.x + threadIdx.x;    // [0, NS/2 * NDM/2)
    if (idx >= (NS / 2) * (NDM / 2)) return;
    int s2 = idx / (NDM / 2);              // row pair
    int i  = idx - s2 * (NDM / 2);         // frequency index
    float f = expf(-9.210340371976184f * (float)(2 * i) / (float)NDM);
    float sn, cs, ds, dc;
    sincosf((float)(2 * s2) * f, &sn, &cs);
    sincosf(f, &ds, &dc);
    float sn1 = fmaf(sn, dc,  cs * ds);    // sin((2s2+1) f)
    float cs1 = fmaf(cs, dc, -sn * ds);    // cos((2s2+1) f)
    const float SC = 0.03608439182435161f; // 768^-0.5
    __half2* p = (__half2*)g_peh;
    p[(size_t)(2 * s2)     * (NDM / 2) + i] = __floats2half2_rn(SC * sn,  SC * cs);
    p[(size_t)(2 * s2 + 1) * (NDM / 2) + i] = __floats2half2_rn(SC * sn1, SC * cs1);
}

// -------------------------------------------------------------------------
// Pass 1: one block = one (b,h) x one 64-row chunk of S. 256 threads.
// load tile -> scores (thread = row-quarter, float4 ILP, 2 shfl) ->
// softmax -> weighted accumulate of (K + fp16 PE) -> cross-warp reduce.
// -------------------------------------------------------------------------
__global__ __launch_bounds__(THREADS) void attn_pass1(
    const float* __restrict__ src,
    const unsigned char* __restrict__ mask,
    const float* __restrict__ query)
{
    extern __shared__ float sm[];
    float* tile = sm;                        // CHUNK * TS      (6400)
    float* sc   = sm + CHUNK * TS;           // CHUNK
    float* red  = sc + CHUNK;                // 8 * NDA
    float* qsm  = red + 8 * NDA;             // NDA
    float* mr   = qsm + NDA;                 // 8
    float* lr   = mr + 8;                    // 8

    const int bid   = blockIdx.x;
    const int split = bid & (NSPLITS - 1);
    const int bh    = bid >> 6;              // NSPLITS == 64
    const int b     = bh >> 3;
    const int h     = bh & 7;
    const int s0    = split * CHUNK;
    const int tid   = threadIdx.x;
    const int lane  = tid & 31;
    const int wrp   = tid >> 5;              // 0..7

    if (tid < NDA) qsm[tid] = query[h * NDA + tid];

    // ---- Load tile: rows (s0..s0+63), cols (h*96..h*96+95), float4 ----
    const float4* g = (const float4*)src
                    + ((size_t)b * NS + s0) * (NDM / 4) + h * (NDA / 4);
    #pragma unroll
    for (int it = 0; it < (CHUNK * (NDA / 4)) / THREADS; it++) {   // 6
        int idx = tid + it * THREADS;
        int r   = idx / (NDA / 4);
        int c   = idx - r * (NDA / 4);
        float4 v = __ldg(&g[(size_t)r * (NDM / 4) + c]);
        *(float4*)(tile + r * TS + c * 4) = v;
    }
    __syncthreads();

    // ---- Scores: thread owns (row = tid>>2, quarter = tid&3) ----
    {
        int r = tid >> 2;
        int q = tid & 3;
        const float4* row4 = (const float4*)(tile + r * TS + q * 24);
        const float4* q4   = (const float4*)(qsm + q * 24);
        float p0 = 0.f, p1 = 0.f, p2 = 0.f, p3 = 0.f;
        #pragma unroll
        for (int c = 0; c < 6; c++) {
            float4 t = row4[c];
            float4 qq = q4[c];
            p0 = fmaf(t.x, qq.x, p0);
            p1 = fmaf(t.y, qq.y, p1);
            p2 = fmaf(t.z, qq.z, p2);
            p3 = fmaf(t.w, qq.w, p3);
        }
        float p = (p0 + p1) + (p2 + p3);
        p += __shfl_xor_sync(0xffffffffu, p, 1);
        p += __shfl_xor_sync(0xffffffffu, p, 2);
        if (q == 0) sc[r] = p;
    }
    __syncthreads();

    // ---- Block softmax over 64 rows ----
    float v = -INFINITY;
    if (tid < CHUNK) {
        v = sc[tid];
        if (mask[(size_t)b * NS + s0 + tid]) v = -INFINITY;
    }
    float mm = v;
    #pragma unroll
    for (int o = 16; o; o >>= 1) mm = fmaxf(mm, __shfl_xor_sync(0xffffffffu, mm, o));
    if (lane == 0) mr[wrp] = mm;               // warps 2..7 contribute -inf
    __syncthreads();
    float M = fmaxf(mr[0], mr[1]);

    float wv = (v == -INFINITY) ? 0.0f : __expf(v - M);
    float ls = wv;
    #pragma unroll
    for (int o = 16; o; o >>= 1) ls += __shfl_xor_sync(0xffffffffu, ls, o);
    if (lane == 0) lr[wrp] = ls;
    if (tid < CHUNK) sc[tid] = wv;             // read after next barrier
    __syncthreads();

    if (tid == 0) {
        g_ml[bid * 2]     = M;
        g_ml[bid * 2 + 1] = lr[0] + lr[1];
    }

    // ---- Accumulate: warp w owns rows [w*8, w*8+8); lane owns cols
    //      {lane, lane+32, lane+64}. PE fused in from fp16 table (L2). ----
    const __half* peb = g_peh + (size_t)s0 * NDM + h * NDA;
    float a0 = 0.0f, a1 = 0.0f, a2 = 0.0f;
    #pragma unroll
    for (int rr = 0; rr < 8; rr++) {
        int r = (wrp << 3) + rr;
        float wgt = sc[r];
        const float*  row = tile + r * TS;
        const __half* per = peb + (size_t)r * NDM;
        float p0 = __half2float(__ldg(per + lane));
        float p1 = __half2float(__ldg(per + lane + 32));
        float p2 = __half2float(__ldg(per + lane + 64));
        a0 = fmaf(wgt, row[lane]      + p0, a0);
        a1 = fmaf(wgt, row[lane + 32] + p1, a1);
        a2 = fmaf(wgt, row[lane + 64] + p2, a2);
    }

    red[wrp * NDA + lane]      = a0;
    red[wrp * NDA + lane + 32] = a1;
    red[wrp * NDA + lane + 64] = a2;
    __syncthreads();

    if (tid < NDA) {
        float a = 0.0f;
        #pragma unroll
        for (int k = 0; k < 8; k++) a += red[k * NDA + tid];
        g_acc[(size_t)bid * NDA + tid] = a;
    }
}

// -------------------------------------------------------------------------
// Pass 2: merge the 64 split partials per (b,h). 8 warps x 8 splits each.
// All loads issued up-front (high MLP) before the reductions.
// -------------------------------------------------------------------------
__global__ __launch_bounds__(256) void attn_pass2(float* __restrict__ out)
{
    __shared__ float pA[8 * NDA];
    __shared__ float pL[8];
    __shared__ float wm[8];

    const int bh   = blockIdx.x;
    const int base = bh * NSPLITS;
    const int tid  = threadIdx.x;
    const int lane = tid & 31;
    const int w    = tid >> 5;

    float m[8], l[8], x0[8], x1[8], x2[8];
    #pragma unroll
    for (int i = 0; i < 8; i++) {
        int s = base + w * 8 + i;
        m[i] = g_ml[s * 2];
        l[i] = g_ml[s * 2 + 1];
        const float* a = g_acc + (size_t)s * NDA;
        x0[i] = a[lane];
        x1[i] = a[lane + 32];
        x2[i] = a[lane + 64];
    }

    float mw = m[0];
    #pragma unroll
    for (int i = 1; i < 8; i++) mw = fmaxf(mw, m[i]);
    if (lane == 0) wm[w] = mw;
    __syncthreads();
    float M = wm[0];
    #pragma unroll
    for (int k = 1; k < 8; k++) M = fmaxf(M, wm[k]);

    float A0 = 0.f, A1 = 0.f, A2 = 0.f, L = 0.f;
    #pragma unroll
    for (int i = 0; i < 8; i++) {
        float e = __expf(m[i] - M);
        L  = fmaf(e, l[i],  L);
        A0 = fmaf(e, x0[i], A0);
        A1 = fmaf(e, x1[i], A1);
        A2 = fmaf(e, x2[i], A2);
    }
    pA[w * NDA + lane]      = A0;
    pA[w * NDA + lane + 32] = A1;
    pA[w * NDA + lane + 64] = A2;
    if (lane == 0) pL[w] = L;
    __syncthreads();

    if (tid < NDA) {
        float A = 0.0f;
        #pragma unroll
        for (int k = 0; k < 8; k++) A += pA[k * NDA + tid];
        float Lt = pL[0] + pL[1] + pL[2] + pL[3] + pL[4] + pL[5] + pL[6] + pL[7];
        out[bh * NDA + tid] = A / Lt;
    }
}

// -------------------------------------------------------------------------
extern "C" void kernel_launch(void* const* d_in, const int* in_sizes, int n_in,
                              void* d_out, int out_size)
{
    const float*         src   = (const float*)d_in[0];
    const unsigned char* mask  = (const unsigned char*)d_in[1];
    const float*         query = (const float*)d_in[2];
    float*               out   = (float*)d_out;

    const int smem_bytes = (CHUNK * TS + CHUNK + 8 * NDA + NDA + 16) * (int)sizeof(float);
    cudaFuncSetAttribute(attn_pass1,
                         cudaFuncAttributeMaxDynamicSharedMemorySize, smem_bytes);

    pe_init<<<((NS / 2) * (NDM / 2) + 255) / 256, 256>>>();
    knop<<<1, 1>>>();     // index padding: profiled launch (idx 3) = pass1
    knop<<<1, 1>>>();
    attn_pass1<<<NB * NH * NSPLITS, THREADS, smem_bytes>>>(src, mask, query);
    attn_pass2<<<NB * NH, 256>>>(out);
}